// round 13
// baseline (speedup 1.0000x reference)
#include <cuda_runtime.h>
#include <cstdint>

// Problem constants
#define NTOT 8192            // B*N patch tiles
#define INV_TEMP 10.0f
#define LN_EPS 1e-5f

// One WARP handles one whole patch: matvec + LN + softmax + affine + store.
// No shared memory, no __syncthreads, no inter-CTA coupling.
// Chunks are software-pipelined: chunk c+1's loads are in flight during chunk c's reduce.
__global__ __launch_bounds__(128, 6)
void scs_warp(const float* __restrict__ spikes,
              const float* __restrict__ Wd,
              const float* __restrict__ gamma,
              const float* __restrict__ beta,
              const float* __restrict__ gates,
              const float* __restrict__ biases,
              float* __restrict__ out) {
    const int l   = threadIdx.x & 31;
    const int wid = threadIdx.x >> 5;
    const int g   = (blockIdx.x << 2) + wid;      // patch tile
    const int b   = g >> 10;
    const int n   = g & 1023;
    const int py  = n >> 5;
    const int px  = n & 31;

    // ---- front-issue chunk 0's W loads (warp-contiguous 512B per instr) ----
    const float4* Wp = (const float4*)(Wd + ((size_t)g << 12));
    float4 w0 = __ldcs(Wp + l);
    float4 w1 = __ldcs(Wp + l + 32);
    float4 w2 = __ldcs(Wp + l + 64);
    float4 w3 = __ldcs(Wp + l + 96);

    // ---- patch float4: lane l takes part jq = l&15 (two halves duplicate) ----
    const int jq = l & 15;
    const float4 p = __ldg((const float4*)(spikes + ((size_t)b << 16)
                                           + ((py << 3) + (jq >> 1)) * 256
                                           + (px << 3) + ((jq & 1) << 2)));

    // patch spike mass: reduce over the 16 parts (overlaps chunk-0 load wait)
    float ps = p.x + p.y + p.z + p.w;
    ps += __shfl_xor_sync(0xffffffffu, ps, 1);
    ps += __shfl_xor_sync(0xffffffffu, ps, 2);
    ps += __shfl_xor_sync(0xffffffffu, ps, 4);
    ps += __shfl_xor_sync(0xffffffffu, ps, 8);

    const bool b2 = (l >> 2) & 1;
    const bool b3 = (l >> 3) & 1;
    const int  d  = ((l >> 2) & 1) * 4 + ((l >> 3) & 1) * 2 + (l >> 4);  // 0..7

    // ---- matvec: 8 chunks, software-pipelined; each yields ONE reduced row/lane ----
    // f = l + 32k, k = 4c+j  ->  row(f) = 8c + 2j + (l>>4), part(f) = l&15
    float R[8];
#pragma unroll
    for (int c = 0; c < 8; ++c) {
        // prefetch chunk c+1 while chunk c computes
        float4 n0 = w0, n1 = w1, n2 = w2, n3 = w3;
        if (c < 7) {
            const float4* q = Wp + l + 128 * (c + 1);
            n0 = __ldcs(q);
            n1 = __ldcs(q + 32);
            n2 = __ldcs(q + 64);
            n3 = __ldcs(q + 96);
        }

        const float a0 = w0.x * p.x + w0.y * p.y + w0.z * p.z + w0.w * p.w; // row 8c+0+h
        const float a1 = w1.x * p.x + w1.y * p.y + w1.z * p.z + w1.w * p.w; // row 8c+2+h
        const float a2 = w2.x * p.x + w2.y * p.y + w2.z * p.z + w2.w * p.w; // row 8c+4+h
        const float a3 = w3.x * p.x + w3.y * p.y + w3.z * p.z + w3.w * p.w; // row 8c+6+h

        // distribute-reduce over the 16 parts:
        const float tA = b3 ? a0 : a1, rA = b3 ? a1 : a0;
        const float u0 = rA + __shfl_xor_sync(0xffffffffu, tA, 8);   // row 8c+2*b3+h
        const float tB = b3 ? a2 : a3, rB = b3 ? a3 : a2;
        const float u1 = rB + __shfl_xor_sync(0xffffffffu, tB, 8);   // row 8c+4+2*b3+h
        const float tC = b2 ? u0 : u1, rC = b2 ? u1 : u0;
        float v = rC + __shfl_xor_sync(0xffffffffu, tC, 4);          // row 8c+4*b2+2*b3+h
        v += __shfl_xor_sync(0xffffffffu, v, 2);
        v += __shfl_xor_sync(0xffffffffu, v, 1);
        R[c] = v;                                                    // row 8c+d, full sum

        w0 = n0; w1 = n1; w2 = n2; w3 = n3;
    }

    // ---- LayerNorm stats: local tree + 3 shuffles (o=4,8,16 span bits 2,3,4) ----
    float sm = ((R[0] + R[1]) + (R[2] + R[3])) + ((R[4] + R[5]) + (R[6] + R[7]));
    float s2 = R[0]*R[0] + R[1]*R[1] + R[2]*R[2] + R[3]*R[3]
             + R[4]*R[4] + R[5]*R[5] + R[6]*R[6] + R[7]*R[7];
    sm += __shfl_xor_sync(0xffffffffu, sm, 4);
    s2 += __shfl_xor_sync(0xffffffffu, s2, 4);
    sm += __shfl_xor_sync(0xffffffffu, sm, 8);
    s2 += __shfl_xor_sync(0xffffffffu, s2, 8);
    sm += __shfl_xor_sync(0xffffffffu, sm, 16);
    s2 += __shfl_xor_sync(0xffffffffu, s2, 16);

    const float mu   = sm * (1.0f / 64.0f);
    const float rstd = rsqrtf(s2 * (1.0f / 64.0f) - mu * mu + LN_EPS);

    // ---- z values: row 8c+d uses gamma/beta[8c+d] (L1-hot) ----
#pragma unroll
    for (int c = 0; c < 8; ++c) {
        const float gm = __ldg(&gamma[8 * c + d]);
        const float bt = __ldg(&beta[8 * c + d]);
        R[c] = ((R[c] - mu) * rstd * gm + bt) * INV_TEMP;
    }

    // ---- softmax: max ----
    float mx = fmaxf(fmaxf(fmaxf(R[0], R[1]), fmaxf(R[2], R[3])),
                     fmaxf(fmaxf(R[4], R[5]), fmaxf(R[6], R[7])));
    mx = fmaxf(mx, __shfl_xor_sync(0xffffffffu, mx, 4));
    mx = fmaxf(mx, __shfl_xor_sync(0xffffffffu, mx, 8));
    mx = fmaxf(mx, __shfl_xor_sync(0xffffffffu, mx, 16));

#pragma unroll
    for (int c = 0; c < 8; ++c)
        R[c] = __expf(R[c] - mx);

    float se = ((R[0] + R[1]) + (R[2] + R[3])) + ((R[4] + R[5]) + (R[6] + R[7]));
    se += __shfl_xor_sync(0xffffffffu, se, 4);
    se += __shfl_xor_sync(0xffffffffu, se, 8);
    se += __shfl_xor_sync(0xffffffffu, se, 16);

    const float scale = (__ldg(&gates[n]) * ps + __ldg(&biases[n])) / se;

    // ---- store: lane writes rows c0 = l&3 and c0+4 (pixel (c, d) of 8x8 patch) ----
    const int c0 = l & 3;
    float e_lo = R[0], e_hi = R[4];
#pragma unroll
    for (int c = 1; c < 4; ++c) {
        if (c0 == c) { e_lo = R[c]; e_hi = R[c + 4]; }
    }
    float* ob = out + ((size_t)b << 16) + (py << 3) * 256 + (px << 3) + d;
    ob[c0 * 256]       = e_lo * scale;
    ob[(c0 + 4) * 256] = e_hi * scale;
}

extern "C" void kernel_launch(void* const* d_in, const int* in_sizes, int n_in,
                              void* d_out, int out_size) {
    const float* spikes = (const float*)d_in[0];
    const float* Wd     = (const float*)d_in[1];
    const float* gamma  = (const float*)d_in[2];
    const float* beta   = (const float*)d_in[3];
    const float* gates  = (const float*)d_in[4];
    const float* biases = (const float*)d_in[5];
    float* out = (float*)d_out;

    scs_warp<<<NTOT / 4, 128>>>(spikes, Wd, gamma, beta, gates, biases, out);
}